// round 16
// baseline (speedup 1.0000x reference)
#include <cuda_runtime.h>
#include <cstdint>

#define N1 8112
#define N2 2028
#define N3 507
#define NANCH 10647
#define NB 8
#define NC 80
#define KTOP 256
#define CAND 512
#define MAXPC 100
#define MAXTOT 100
#define SCORE_THR 0.3f
#define IOU_THR 0.5f
#define NEGV -1000000000.0f
#define PTHR 0.74f
#define STH2 0.82f
#define TTHR 0.978f
#define ACAP 4096
#define FBINS 2048
#define CCAP 320
#define JMAX 32
#define NPAIRS 8128   /* 128*127/2 */

__device__ uint2 g_l74[NB][ACAP];
__device__ int   g_n74[NB];
__device__ unsigned long long g_cand[NB][NC][CCAP];
__device__ int   g_candn[NB][NC];
__device__ unsigned long long g_topc[NB][KTOP];
__device__ int   g_ntop[NB];
__device__ int   g_done[NB];
__device__ float  g_sc[NB][NC * MAXPC];
__device__ float4 g_box[NB][NC * MAXPC];
__device__ int    g_cnt[NB][NC];

__device__ __forceinline__ void anchor_base(
    unsigned a, int b,
    const float* p1, const float* p2, const float* p3,
    const float** pp, int* o)
{
    if (a < N1)           { *pp = p1; *o = b * N1 + (int)a; }
    else if (a < N1 + N2) { *pp = p2; *o = b * N2 + ((int)a - N1); }
    else                  { *pp = p3; *o = b * N3 + ((int)a - N1 - N2); }
}

// ---------------------------------------------------------------------------
// Kernel A: compact conf>0.74 anchors. grid (42, 8) x 256.
// ---------------------------------------------------------------------------
__global__ __launch_bounds__(256) void compact_kernel(
    const float* __restrict__ c1, const float* __restrict__ c2,
    const float* __restrict__ c3)
{
    __shared__ int wcnt[8];
    __shared__ int wbase[8];

    const int b   = blockIdx.y;
    const int a   = blockIdx.x * 256 + threadIdx.x;
    const int tid = threadIdx.x;
    const int wid = tid >> 5;
    const int lane = tid & 31;
    const unsigned ltmask = (1u << lane) - 1u;

    float cf = 0.0f;
    if (a < NANCH) {
        if (a < N1)           cf = c1[b * N1 + a];
        else if (a < N1 + N2) cf = c2[b * N2 + (a - N1)];
        else                  cf = c3[b * N3 + (a - N1 - N2)];
    }
    bool p74 = cf > PTHR;
    unsigned m = __ballot_sync(0xFFFFFFFFu, p74);
    if (lane == 0) wcnt[wid] = __popc(m);
    __syncthreads();
    if (tid == 0) {
        int tot = 0;
        int pre[8];
#pragma unroll
        for (int w = 0; w < 8; w++) { pre[w] = tot; tot += wcnt[w]; }
        int base = (tot > 0) ? atomicAdd(&g_n74[b], tot) : 0;
#pragma unroll
        for (int w = 0; w < 8; w++) wbase[w] = base + pre[w];
    }
    __syncthreads();
    if (p74) {
        int pos = wbase[wid] + __popc(m & ltmask);
        if (pos < ACAP)
            g_l74[b][pos] = make_uint2((unsigned)a, __float_as_uint(cf));
    }
}

// ---------------------------------------------------------------------------
// Kernel B: score + filter. grid (64, 8) x 256. (R14/R15, measured-good)
// ---------------------------------------------------------------------------
__global__ __launch_bounds__(256) void score_filter_kernel(
    const float* __restrict__ p1, const float* __restrict__ p2,
    const float* __restrict__ p3)
{
    __shared__ float tile[64][NC + 1];
    __shared__ unsigned aidx[64];
    __shared__ int s_acnt;

    const int b   = blockIdx.y;
    const int j0  = blockIdx.x * 64;
    const int tid = threadIdx.x;
    const int wid = tid >> 5;
    const int lane = tid & 31;
    const unsigned ltmask = (1u << lane) - 1u;

    if (tid == 0) {
        int n = g_n74[b];
        s_acnt = n > ACAP ? ACAP : n;
    }
    __syncthreads();
    const int acnt = s_acnt;
    if (j0 >= acnt) return;

    if (tid < 64) {
        int j = j0 + tid;
        uint2 e = (j < acnt) ? g_l74[b][j] : make_uint2(0u, 0u);
        aidx[tid] = e.x;
        tile[tid][NC] = (j < acnt) ? __uint_as_float(e.y) : 0.0f;
    }
    __syncthreads();

#pragma unroll
    for (int k = 0; k < 5; k++) {
        int idx = tid + k * 256;
        int al = idx / 20;
        int q  = idx - al * 20;
        float cf = tile[al][NC];
        float4 v = make_float4(0.f, 0.f, 0.f, 0.f);
        if (cf > 0.0f) {
            const float* pp; int o;
            anchor_base(aidx[al], b, p1, p2, p3, &pp, &o);
            v = *reinterpret_cast<const float4*>(pp + (size_t)o * NC + q * 4);
        }
        tile[al][q * 4 + 0] = v.x * cf;
        tile[al][q * 4 + 1] = v.y * cf;
        tile[al][q * 4 + 2] = v.z * cf;
        tile[al][q * 4 + 3] = v.w * cf;
    }
    __syncthreads();

    unsigned m0s[10], m1s[10];
    int myTot = 0;
#pragma unroll
    for (int t = 0; t < 10; t++) {
        int c = wid + t * 8;
        bool q0 = tile[lane][c] > STH2;
        bool q1 = tile[32 + lane][c] > STH2;
        m0s[t] = __ballot_sync(0xFFFFFFFFu, q0);
        m1s[t] = __ballot_sync(0xFFFFFFFFu, q1);
        int tot = __popc(m0s[t]) + __popc(m1s[t]);
        if (lane == t) myTot = tot;
    }
    int myBase = 0;
    if (lane < 10 && myTot > 0)
        myBase = atomicAdd(&g_candn[b][wid + lane * 8], myTot);

#pragma unroll
    for (int t = 0; t < 10; t++) {
        int c = wid + t * 8;
        unsigned m0 = m0s[t], m1 = m1s[t];
        if ((m0 | m1) == 0u) continue;
        int base = __shfl_sync(0xFFFFFFFFu, myBase, t);
        int n0 = __popc(m0);
        if ((m0 >> lane) & 1u) {
            int pos = base + __popc(m0 & ltmask);
            if (pos < CCAP)
                g_cand[b][c][pos] =
                    ((unsigned long long)__float_as_uint(tile[lane][c]) << 32)
                    | (unsigned)(~aidx[lane]);
        }
        if ((m1 >> lane) & 1u) {
            int pos = base + n0 + __popc(m1 & ltmask);
            if (pos < CCAP)
                g_cand[b][c][pos] =
                    ((unsigned long long)__float_as_uint(tile[32 + lane][c]) << 32)
                    | (unsigned)(~aidx[32 + lane]);
        }
    }
}

// ---------------------------------------------------------------------------
// Kernel C: per-(image,class) NMS + fused per-image top-100 (last block).
// ---------------------------------------------------------------------------
__global__ __launch_bounds__(256) void nms_class_kernel(
    const float* __restrict__ b1, const float* __restrict__ b2,
    const float* __restrict__ b3,
    const float* __restrict__ c1, const float* __restrict__ c2,
    const float* __restrict__ c3,
    const float* __restrict__ p1, const float* __restrict__ p2,
    const float* __restrict__ p3,
    float* __restrict__ out)
{
    __shared__ unsigned long long keys[CAND];                 // 4 KB (reused: keys2)
    __shared__ __align__(16) float4 cbox4[KTOP];              // 4 KB
    __shared__ float carea[KTOP], csc[KTOP];
    __shared__ int   keptslot[KTOP];
    __shared__ __align__(16) unsigned suppT[128 * 4];         // 2 KB (transposed)
    __shared__ __align__(16) unsigned supp8[KTOP * 8];        // 8 KB (fallback/hist2)
    __shared__ int hist[256];                                 // (fallback/gsum)
    __shared__ int misc[16];
    __shared__ unsigned validm[8];
    __shared__ unsigned kw[4];
    __shared__ int schanged;

    const int b    = blockIdx.x / NC;
    const int c    = blockIdx.x % NC;
    const int tid  = threadIdx.x;
    const int lane = tid & 31;
    const unsigned ltmask = (1u << lane) - 1u;

    if (tid == 0) {
        misc[3] = 0; misc[12] = 0;
        misc[5] = g_candn[b][c];
        misc[6] = g_n74[b];
    }
    __syncthreads();

    const int cnt0 = misc[5];
    const bool good0 = (misc[6] <= ACAP) && (cnt0 >= 128 && cnt0 <= KTOP);

    if (good0) {
        // ---- direct load + hybrid bitonic sort of 256 keys, descending ----
        unsigned long long r = (tid < cnt0) ? g_cand[b][c][tid] : 0ull;
#pragma unroll
        for (int k = 2; k <= KTOP; k <<= 1) {
            for (int j = k >> 1; j > 0; j >>= 1) {
                unsigned long long v;
                if (j >= 32) {
                    keys[tid] = r;
                    __syncthreads();
                    v = keys[tid ^ j];
                    __syncthreads();
                } else {
                    v = __shfl_xor_sync(0xFFFFFFFFu, r, j);
                }
                bool up = ((tid & k) == 0) == ((tid & j) == 0);
                r = up ? (r > v ? r : v) : (r < v ? r : v);
            }
        }
        keys[tid] = r;
        __syncthreads();

        // ---- load boxes for top-256 ----
        unsigned long long mykey = r;
        bool valid = (mykey != 0ull);
        float sc = __uint_as_float((unsigned)(mykey >> 32));
        float4 bx = make_float4(0.f, 0.f, 0.f, 0.f);
        if (valid) {
            unsigned a = ~(unsigned)(mykey & 0xFFFFFFFFu);
            const float* bp; size_t off;
            if (a < N1)           { bp = b1; off = (size_t)(b * N1 + a) * 4; }
            else if (a < N1 + N2) { bp = b2; off = (size_t)(b * N2 + (a - N1)) * 4; }
            else                  { bp = b3; off = (size_t)(b * N3 + (a - N1 - N2)) * 4; }
            bx = *reinterpret_cast<const float4*>(bp + off);
        }
        cbox4[tid] = bx;
        carea[tid] = (bx.z - bx.x) * (bx.w - bx.y);
        csc[tid] = sc;
        keptslot[tid] = -1;
        {
            unsigned bal = __ballot_sync(0xFFFFFFFFu, valid);
            if (lane == 0) validm[tid >> 5] = bal;
        }
        if (tid < 128) {
            *reinterpret_cast<uint4*>(&suppT[tid * 4]) = make_uint4(0u, 0u, 0u, 0u);
        }
        __syncthreads();

        // ---- balanced triangle: 256 threads x 32 flat pairs each.
        //      suppT column-major: column j holds bits i<j. Division-free
        //      exact test (same arithmetic / ambiguity flag as before). ----
        {
            int f = tid * 32;
            int fend = f + 32;
            if (fend > NPAIRS) fend = NPAIRS;
            if (f < fend) {
                // unrank: largest j with j(j-1)/2 <= f
                int j = (int)((1.0f + sqrtf(8.0f * (float)f + 1.0f)) * 0.5f);
                while ((j * (j - 1)) / 2 > f) j--;
                while ((j * (j + 1)) / 2 <= f) j++;
                int i = f - (j * (j - 1)) / 2;
                float4 bj = cbox4[j];
                float aj = carea[j];
                int curw = i >> 5;
                unsigned acc = 0u;
                for (int p = f; p < fend; p++) {
                    float4 bi = cbox4[i];
                    float ai = carea[i];
                    float iy = fmaxf(fminf(bi.z, bj.z) - fmaxf(bi.x, bj.x), 0.0f);
                    float ix = fmaxf(fminf(bi.w, bj.w) - fmaxf(bi.y, bj.y), 0.0f);
                    float inter = iy * ix;
                    float uni = (ai + aj) - inter;
                    float hu  = 0.5f * uni;
                    if (inter > hu) {
                        if (inter > hu * 1.0000002f) {
                            acc |= 1u << (i & 31);
                        } else {
                            misc[12] = 1;   // ambiguous rounding band
                        }
                    }
                    i++;
                    if (i == j) {
                        if (acc) atomicOr(&suppT[j * 4 + curw], acc);
                        acc = 0u; curw = 0;
                        j++; i = 0;
                        if (p + 1 < fend) { bj = cbox4[j]; aj = carea[j]; }
                    } else if ((i >> 5) != curw) {
                        if (acc) atomicOr(&suppT[j * 4 + curw], acc);
                        acc = 0u; curw = i >> 5;
                    }
                }
                if (acc) atomicOr(&suppT[j * 4 + curw], acc);
            }
        }
        if (tid < 4) kw[tid] = validm[tid];   // x^0 = valid
        __syncthreads();

        // ---- Jacobi fixpoint: x_j = valid_j & !OR_{i<j}(suppT[j][i] & x_i).
        // Unique fixpoint == greedy NMS keep set; no-change => exact. ----
        {
            uint4 sa = make_uint4(0u, 0u, 0u, 0u);
            bool vj = false;
            if (tid < 128) {
                sa = *reinterpret_cast<const uint4*>(&suppT[tid * 4]);
                vj = (validm[tid >> 5] >> (tid & 31)) & 1u;
            }
            int it = 0;
            for (; it < JMAX; it++) {
                unsigned k0 = kw[0], k1 = kw[1], k2 = kw[2], k3 = kw[3];
                bool nx = false;
                if (tid < 128) {
                    unsigned hitb = (sa.x & k0) | (sa.y & k1)
                                  | (sa.z & k2) | (sa.w & k3);
                    nx = vj && (hitb == 0u);
                }
                unsigned m = __ballot_sync(0xFFFFFFFFu, nx);
                __syncthreads();
                if (tid == 0) schanged = 0;
                __syncthreads();
                if (tid < 128 && lane == 0) {
                    if (m != kw[tid >> 5]) { kw[tid >> 5] = m; atomicOr(&schanged, 1); }
                }
                __syncthreads();
                if (!schanged) break;
            }
            if (it == JMAX && tid == 0) misc[12] = 1;
        }
        __syncthreads();

        // ---- rank kept candidates, gate on total>=100 ----
        if (misc[12] == 0) {
            unsigned k0 = kw[0], k1 = kw[1], k2 = kw[2], k3 = kw[3];
            int total = __popc(k0) + __popc(k1) + __popc(k2) + __popc(k3);
            if (tid < 128) {
                int w = tid >> 5;
                unsigned kwv = (w == 0) ? k0 : (w == 1) ? k1 : (w == 2) ? k2 : k3;
                if ((kwv >> (tid & 31)) & 1u) {
                    int rank = __popc(kwv & ((1u << (tid & 31)) - 1u));
                    if (w > 0) rank += __popc(k0);
                    if (w > 1) rank += __popc(k1);
                    if (w > 2) rank += __popc(k2);
                    if (rank < MAXPC) keptslot[tid] = rank;
                }
            }
            if (tid == 0) {
                if (total >= MAXPC) {
                    misc[3] = 1; misc[2] = MAXPC; g_cnt[b][c] = MAXPC;
                } else {
                    misc[3] = 0;
                }
            }
        }
        __syncthreads();
    }

    // ---- full exact fallback (never taken for this data) ----
    if (!good0 || misc[12] || !misc[3]) {
        hist[tid] = 0;
        if (tid == 0) { misc[1] = 0; misc[2] = 0; }
        keys[tid] = 0ull;
        keys[tid + 256] = 0ull;
        keptslot[tid] = -1;
        __syncthreads();
        for (int a = tid; a < NANCH; a += 256) {
            float cf;
            const float* pp; int o;
            if (a < N1)           { cf = c1[b * N1 + a]; pp = p1; o = b * N1 + a; }
            else if (a < N1 + N2) { cf = c2[b * N2 + (a - N1)]; pp = p2; o = b * N2 + (a - N1); }
            else                  { cf = c3[b * N3 + (a - N1 - N2)]; pp = p3; o = b * N3 + (a - N1 - N2); }
            if (cf > SCORE_THR) {
                float s = cf * __ldg(pp + (size_t)o * NC + c);
                if (s > SCORE_THR) {
                    int bk = (int)((s - SCORE_THR) * (256.0f / 0.7f));
                    bk = bk > 255 ? 255 : (bk < 0 ? 0 : bk);
                    atomicAdd(&hist[bk], 1);
                }
            }
        }
        __syncthreads();
        if (tid == 0) {
            int acc = 0, bbv = 0;
            for (int i = 255; i >= 0; --i) {
                acc += hist[i];
                if (acc >= KTOP) { bbv = i; break; }
            }
            misc[1] = bbv;
        }
        __syncthreads();
        const int bbv = misc[1];
        const int napad = (NANCH + 255) & ~255;
        for (int a = tid; a < napad; a += 256) {
            float s = 0.0f;
            bool pred = false;
            if (a < NANCH) {
                float cf;
                const float* pp; int o;
                if (a < N1)           { cf = c1[b * N1 + a]; pp = p1; o = b * N1 + a; }
                else if (a < N1 + N2) { cf = c2[b * N2 + (a - N1)]; pp = p2; o = b * N2 + (a - N1); }
                else                  { cf = c3[b * N3 + (a - N1 - N2)]; pp = p3; o = b * N3 + (a - N1 - N2); }
                if (cf > SCORE_THR) {
                    s = cf * __ldg(pp + (size_t)o * NC + c);
                    if (s > SCORE_THR) {
                        int bk = (int)((s - SCORE_THR) * (256.0f / 0.7f));
                        bk = bk > 255 ? 255 : (bk < 0 ? 0 : bk);
                        pred = (bk >= bbv);
                    }
                }
            }
            unsigned m = __ballot_sync(0xFFFFFFFFu, pred);
            if (pred) {
                int rank = __popc(m & ltmask);
                int base;
                if (rank == 0) base = atomicAdd(&misc[2], __popc(m));
                base = __shfl_sync(m, base, __ffs(m) - 1);
                int pos = base + rank;
                if (pos < CAND)
                    keys[pos] = ((unsigned long long)__float_as_uint(s) << 32)
                                | (unsigned)(~(unsigned)a);
            }
        }
        __syncthreads();
        if (tid == 0) misc[2] = 0;

        for (int k = 2; k <= CAND; k <<= 1) {
            for (int j = k >> 1; j > 0; j >>= 1) {
                int i = ((tid & ~(j - 1)) << 1) | (tid & (j - 1));
                int p = i | j;
                unsigned long long va = keys[i], vb = keys[p];
                if ((va < vb) == ((i & k) == 0)) { keys[i] = vb; keys[p] = va; }
                __syncthreads();
            }
        }

        unsigned long long mykey = keys[tid];
        bool valid = (mykey != 0ull);
        float sc = __uint_as_float((unsigned)(mykey >> 32));
        float4 bx = make_float4(0.f, 0.f, 0.f, 0.f);
        if (valid) {
            unsigned a = ~(unsigned)(mykey & 0xFFFFFFFFu);
            const float* bp; size_t off;
            if (a < N1)           { bp = b1; off = (size_t)(b * N1 + a) * 4; }
            else if (a < N1 + N2) { bp = b2; off = (size_t)(b * N2 + (a - N1)) * 4; }
            else                  { bp = b3; off = (size_t)(b * N3 + (a - N1 - N2)) * 4; }
            bx = *reinterpret_cast<const float4*>(bp + off);
        }
        cbox4[tid] = bx;
        carea[tid] = (bx.z - bx.x) * (bx.w - bx.y);
        csc[tid] = sc;
        keptslot[tid] = -1;
        {
            unsigned bal = __ballot_sync(0xFFFFFFFFu, valid);
            if (lane == 0) validm[tid >> 5] = bal;
        }
        __syncthreads();

        {
            const int i = tid;
            const float4 bi = cbox4[i];
            const float areai = carea[i];
            unsigned words[8];
#pragma unroll
            for (int w = 0; w < 8; w++) words[w] = 0u;
            for (int j = i + 1; j < KTOP; j++) {
                float4 bj = cbox4[j];
                float aj = carea[j];
                float iy = fmaxf(fminf(bi.z, bj.z) - fmaxf(bi.x, bj.x), 0.0f);
                float ix = fmaxf(fminf(bi.w, bj.w) - fmaxf(bi.y, bj.y), 0.0f);
                float inter = iy * ix;
                float uni = (areai + aj) - inter;
                if (uni > 0.0f) {
                    float iou = inter / uni;
                    if (iou > IOU_THR) words[j >> 5] |= (1u << (j & 31));
                }
            }
            uint4* sp = reinterpret_cast<uint4*>(&supp8[i * 8]);
            sp[0] = make_uint4(words[0], words[1], words[2], words[3]);
            sp[1] = make_uint4(words[4], words[5], words[6], words[7]);
        }
        __syncthreads();
        if (tid == 0) {
            unsigned kk[8];
#pragma unroll
            for (int w = 0; w < 8; w++) kk[w] = validm[w];
            int count = 0;
            for (int w = 0; w < 8; w++) {
                unsigned cw = kk[w];
                while (cw) {
                    int bit = __ffs(cw) - 1;
                    int i2 = (w << 5) + bit;
                    count++;
                    if (count <= MAXPC) keptslot[i2] = count - 1;
                    uint4 r0 = *reinterpret_cast<const uint4*>(&supp8[i2 * 8]);
                    uint4 r1 = *reinterpret_cast<const uint4*>(&supp8[i2 * 8 + 4]);
                    kk[0] &= ~r0.x; kk[1] &= ~r0.y; kk[2] &= ~r0.z; kk[3] &= ~r0.w;
                    kk[4] &= ~r1.x; kk[5] &= ~r1.y; kk[6] &= ~r1.z; kk[7] &= ~r1.w;
                    unsigned above = (bit == 31) ? 0u : (0xFFFFFFFFu << (bit + 1));
                    cw = kk[w] & above;
                }
            }
            int cc2 = count > MAXPC ? MAXPC : count;
            misc[2] = cc2;
            g_cnt[b][c] = cc2;
        }
        __syncthreads();
    }

    // ---- epilogue: kept writes + NEG tail + topk candidate append ----
    {
        int r2 = keptslot[tid];
        bool kept = (r2 >= 0 && r2 < MAXPC);
        if (kept) {
            g_sc[b][c * MAXPC + r2]  = csc[tid];
            g_box[b][c * MAXPC + r2] = cbox4[tid];
        }
        int cf = misc[2];
        if (tid >= cf && tid < MAXPC) g_sc[b][c * MAXPC + tid] = NEGV;

        bool tp = kept && (csc[tid] > TTHR);
        unsigned m = __ballot_sync(0xFFFFFFFFu, tp);
        if (tp) {
            int rank = __popc(m & ltmask);
            int base;
            if (rank == 0) base = atomicAdd(&g_ntop[b], __popc(m));
            base = __shfl_sync(m, base, __ffs(m) - 1);
            int pos = base + rank;
            if (pos < KTOP) {
                unsigned s_idx = (unsigned)(c * MAXPC + r2);
                g_topc[b][pos] = ((unsigned long long)__float_as_uint(csc[tid]) << 32)
                                 | (unsigned)(~s_idx);
            }
        }
    }

    // ---- last-block-done: fused per-image top-100 ----
    __threadfence();
    __syncthreads();
    if (tid == 0) misc[7] = atomicAdd(&g_done[b], 1);
    __syncthreads();
    if (misc[7] != NC - 1) return;

    unsigned long long* keys2 = keys;
    int* hist2 = reinterpret_cast<int*>(supp8);
    int* gsum  = hist;

    if (tid == 0) { misc[8] = 0; misc[9] = 0; misc[10] = g_ntop[b]; }
    __syncthreads();
    if (tid < NC) atomicAdd(&misc[9], g_cnt[b][tid]);

    const int gcnt = misc[10];
    const bool tgood = (gcnt >= MAXTOT && gcnt <= KTOP);

    if (tgood) {
        unsigned long long r = (tid < gcnt) ? g_topc[b][tid] : 0ull;
#pragma unroll
        for (int k = 2; k <= KTOP; k <<= 1) {
            for (int j = k >> 1; j > 0; j >>= 1) {
                unsigned long long v;
                if (j >= 32) {
                    keys2[tid] = r;
                    __syncthreads();
                    v = keys2[tid ^ j];
                    __syncthreads();
                } else {
                    v = __shfl_xor_sync(0xFFFFFFFFu, r, j);
                }
                bool up = ((tid & k) == 0) == ((tid & j) == 0);
                r = up ? (r > v ? r : v) : (r < v ? r : v);
            }
        }
        keys2[tid] = r;
        __syncthreads();
    } else {
        const float4* gs4 = reinterpret_cast<const float4*>(&g_sc[b][0]);
#pragma unroll
        for (int k = 0; k < 8; k++) hist2[tid + k * 256] = 0;
        keys2[tid] = 0ull;
        keys2[tid + 256] = 0ull;
        __syncthreads();
#pragma unroll
        for (int k = 0; k < 8; k++) {
            int t = tid + k * 256;
            if (t < (NC * MAXPC) / 4) {
                float4 v = gs4[t];
                float sv[4] = {v.x, v.y, v.z, v.w};
#pragma unroll
                for (int q = 0; q < 4; q++) {
                    float s = sv[q];
                    if (s > SCORE_THR) {
                        int bk = (int)((s - SCORE_THR) * ((float)FBINS / 0.7f));
                        bk = bk > FBINS - 1 ? FBINS - 1 : (bk < 0 ? 0 : bk);
                        atomicAdd(&hist2[bk], 1);
                    }
                }
            }
        }
        __syncthreads();
        if (tid < 64) {
            int s = 0;
#pragma unroll
            for (int k = 0; k < 32; k++) s += hist2[tid * 32 + k];
            gsum[tid] = s;
        }
        __syncthreads();
        if (tid == 0) {
            int acc = 0, g = -1, bbv = 0;
            for (int i = 63; i >= 0; i--) {
                if (acc + gsum[i] >= MAXTOT) { g = i; break; }
                acc += gsum[i];
            }
            if (g >= 0) {
                for (int k = 31; k >= 0; k--) {
                    acc += hist2[g * 32 + k];
                    if (acc >= MAXTOT) { bbv = g * 32 + k; break; }
                }
            }
            misc[11] = bbv;
        }
        __syncthreads();
        const int bb = misc[11];
#pragma unroll
        for (int k = 0; k < 8; k++) {
            int t = tid + k * 256;
            if (t < (NC * MAXPC) / 4) {
                float4 v = gs4[t];
                float sv[4] = {v.x, v.y, v.z, v.w};
#pragma unroll
                for (int q = 0; q < 4; q++) {
                    float s = sv[q];
                    if (s > SCORE_THR) {
                        int bk = (int)((s - SCORE_THR) * ((float)FBINS / 0.7f));
                        bk = bk > FBINS - 1 ? FBINS - 1 : (bk < 0 ? 0 : bk);
                        if (bk >= bb) {
                            int pos = atomicAdd(&misc[8], 1);
                            if (pos < CAND) {
                                unsigned s_idx = (unsigned)(t * 4 + q);
                                keys2[pos] =
                                    ((unsigned long long)__float_as_uint(s) << 32)
                                    | (unsigned)(~s_idx);
                            }
                        }
                    }
                }
            }
        }
        __syncthreads();
        for (int k = 2; k <= CAND; k <<= 1) {
            for (int j = k >> 1; j > 0; j >>= 1) {
                for (int v = tid; v < (CAND >> 1); v += 256) {
                    int i = ((v & ~(j - 1)) << 1) | (v & (j - 1));
                    int p = i | j;
                    unsigned long long va = keys2[i], vb = keys2[p];
                    if ((va < vb) == ((i & k) == 0)) { keys2[i] = vb; keys2[p] = va; }
                }
                __syncthreads();
            }
        }
    }

    float* ob = out;
    float* os = out + NB * MAXTOT * 4;
    float* oc = os + NB * MAXTOT;
    float* on = oc + NB * MAXTOT;

    if (tid < MAXTOT) {
        unsigned long long key = keys2[tid];
        float sco = 0.0f, cl = 0.0f;
        float bx0 = 0.f, bx1 = 0.f, bx2 = 0.f, bx3 = 0.f;
        if (key != 0ull) {
            sco = __uint_as_float((unsigned)(key >> 32));
            unsigned s = ~(unsigned)(key & 0xFFFFFFFFu);
            cl = (float)(s / MAXPC);
            float4 bbx = g_box[b][s];
            bx0 = fminf(fmaxf(bbx.x, 0.0f), 1.0f);
            bx1 = fminf(fmaxf(bbx.y, 0.0f), 1.0f);
            bx2 = fminf(fmaxf(bbx.z, 0.0f), 1.0f);
            bx3 = fminf(fmaxf(bbx.w, 0.0f), 1.0f);
        }
        size_t base = (size_t)(b * MAXTOT + tid) * 4;
        ob[base + 0] = bx0; ob[base + 1] = bx1; ob[base + 2] = bx2; ob[base + 3] = bx3;
        os[b * MAXTOT + tid] = sco;
        oc[b * MAXTOT + tid] = cl;
    }
    if (tid < NC) g_candn[b][tid] = 0;
    if (tid == 0) {
        int tot = misc[9];
        on[b] = (float)(tot > MAXTOT ? MAXTOT : tot);
        g_n74[b] = 0; g_ntop[b] = 0; g_done[b] = 0;
    }
}

extern "C" void kernel_launch(void* const* d_in, const int* in_sizes, int n_in,
                              void* d_out, int out_size)
{
    const float* b1 = (const float*)d_in[0];
    const float* c1 = (const float*)d_in[1];
    const float* p1 = (const float*)d_in[2];
    const float* b2 = (const float*)d_in[3];
    const float* c2 = (const float*)d_in[4];
    const float* p2 = (const float*)d_in[5];
    const float* b3 = (const float*)d_in[6];
    const float* c3 = (const float*)d_in[7];
    const float* p3 = (const float*)d_in[8];

    dim3 cgrid(42, NB);
    compact_kernel<<<cgrid, 256>>>(c1, c2, c3);
    dim3 fgrid(64, NB);
    score_filter_kernel<<<fgrid, 256>>>(p1, p2, p3);
    nms_class_kernel<<<NB * NC, 256>>>(b1, b2, b3, c1, c2, c3,
                                       p1, p2, p3, (float*)d_out);
}

// round 17
// speedup vs baseline: 1.1242x; 1.1242x over previous
#include <cuda_runtime.h>
#include <cstdint>

#define N1 8112
#define N2 2028
#define N3 507
#define NANCH 10647
#define NB 8
#define NC 80
#define KTOP 256
#define CAND 512
#define MAXPC 100
#define MAXTOT 100
#define SCORE_THR 0.3f
#define IOU_THR 0.5f
#define NEGV -1000000000.0f
#define PTHR 0.74f
#define STH2 0.82f
#define TTHR 0.978f
#define ACAP 4096
#define FBINS 2048
#define CCAP 320
#define JMAX 32

__device__ uint2 g_l74[NB][ACAP];
__device__ int   g_n74[NB];
__device__ unsigned long long g_cand[NB][NC][CCAP];
__device__ int   g_candn[NB][NC];
__device__ unsigned long long g_topc[NB][KTOP];
__device__ int   g_ntop[NB];
__device__ int   g_done[NB];
__device__ float  g_sc[NB][NC * MAXPC];
__device__ float4 g_box[NB][NC * MAXPC];
__device__ int    g_cnt[NB][NC];

__device__ __forceinline__ void anchor_base(
    unsigned a, int b,
    const float* p1, const float* p2, const float* p3,
    const float** pp, int* o)
{
    if (a < N1)           { *pp = p1; *o = b * N1 + (int)a; }
    else if (a < N1 + N2) { *pp = p2; *o = b * N2 + ((int)a - N1); }
    else                  { *pp = p3; *o = b * N3 + ((int)a - N1 - N2); }
}

// ---------------------------------------------------------------------------
// Kernel A: compact conf>0.74 anchors. grid (42, 8) x 256.
// ---------------------------------------------------------------------------
__global__ __launch_bounds__(256) void compact_kernel(
    const float* __restrict__ c1, const float* __restrict__ c2,
    const float* __restrict__ c3)
{
    __shared__ int wcnt[8];
    __shared__ int wbase[8];

    const int b   = blockIdx.y;
    const int a   = blockIdx.x * 256 + threadIdx.x;
    const int tid = threadIdx.x;
    const int wid = tid >> 5;
    const int lane = tid & 31;
    const unsigned ltmask = (1u << lane) - 1u;

    float cf = 0.0f;
    if (a < NANCH) {
        if (a < N1)           cf = c1[b * N1 + a];
        else if (a < N1 + N2) cf = c2[b * N2 + (a - N1)];
        else                  cf = c3[b * N3 + (a - N1 - N2)];
    }
    bool p74 = cf > PTHR;
    unsigned m = __ballot_sync(0xFFFFFFFFu, p74);
    if (lane == 0) wcnt[wid] = __popc(m);
    __syncthreads();
    if (tid == 0) {
        int tot = 0;
        int pre[8];
#pragma unroll
        for (int w = 0; w < 8; w++) { pre[w] = tot; tot += wcnt[w]; }
        int base = (tot > 0) ? atomicAdd(&g_n74[b], tot) : 0;
#pragma unroll
        for (int w = 0; w < 8; w++) wbase[w] = base + pre[w];
    }
    __syncthreads();
    if (p74) {
        int pos = wbase[wid] + __popc(m & ltmask);
        if (pos < ACAP)
            g_l74[b][pos] = make_uint2((unsigned)a, __float_as_uint(cf));
    }
}

// ---------------------------------------------------------------------------
// Kernel B: score + filter. grid (64, 8) x 256. (R14/R15, measured-good)
// ---------------------------------------------------------------------------
__global__ __launch_bounds__(256) void score_filter_kernel(
    const float* __restrict__ p1, const float* __restrict__ p2,
    const float* __restrict__ p3)
{
    __shared__ float tile[64][NC + 1];
    __shared__ unsigned aidx[64];
    __shared__ int s_acnt;

    const int b   = blockIdx.y;
    const int j0  = blockIdx.x * 64;
    const int tid = threadIdx.x;
    const int wid = tid >> 5;
    const int lane = tid & 31;
    const unsigned ltmask = (1u << lane) - 1u;

    if (tid == 0) {
        int n = g_n74[b];
        s_acnt = n > ACAP ? ACAP : n;
    }
    __syncthreads();
    const int acnt = s_acnt;
    if (j0 >= acnt) return;

    if (tid < 64) {
        int j = j0 + tid;
        uint2 e = (j < acnt) ? g_l74[b][j] : make_uint2(0u, 0u);
        aidx[tid] = e.x;
        tile[tid][NC] = (j < acnt) ? __uint_as_float(e.y) : 0.0f;
    }
    __syncthreads();

#pragma unroll
    for (int k = 0; k < 5; k++) {
        int idx = tid + k * 256;
        int al = idx / 20;
        int q  = idx - al * 20;
        float cf = tile[al][NC];
        float4 v = make_float4(0.f, 0.f, 0.f, 0.f);
        if (cf > 0.0f) {
            const float* pp; int o;
            anchor_base(aidx[al], b, p1, p2, p3, &pp, &o);
            v = *reinterpret_cast<const float4*>(pp + (size_t)o * NC + q * 4);
        }
        tile[al][q * 4 + 0] = v.x * cf;
        tile[al][q * 4 + 1] = v.y * cf;
        tile[al][q * 4 + 2] = v.z * cf;
        tile[al][q * 4 + 3] = v.w * cf;
    }
    __syncthreads();

    unsigned m0s[10], m1s[10];
    int myTot = 0;
#pragma unroll
    for (int t = 0; t < 10; t++) {
        int c = wid + t * 8;
        bool q0 = tile[lane][c] > STH2;
        bool q1 = tile[32 + lane][c] > STH2;
        m0s[t] = __ballot_sync(0xFFFFFFFFu, q0);
        m1s[t] = __ballot_sync(0xFFFFFFFFu, q1);
        int tot = __popc(m0s[t]) + __popc(m1s[t]);
        if (lane == t) myTot = tot;
    }
    int myBase = 0;
    if (lane < 10 && myTot > 0)
        myBase = atomicAdd(&g_candn[b][wid + lane * 8], myTot);

#pragma unroll
    for (int t = 0; t < 10; t++) {
        int c = wid + t * 8;
        unsigned m0 = m0s[t], m1 = m1s[t];
        if ((m0 | m1) == 0u) continue;
        int base = __shfl_sync(0xFFFFFFFFu, myBase, t);
        int n0 = __popc(m0);
        if ((m0 >> lane) & 1u) {
            int pos = base + __popc(m0 & ltmask);
            if (pos < CCAP)
                g_cand[b][c][pos] =
                    ((unsigned long long)__float_as_uint(tile[lane][c]) << 32)
                    | (unsigned)(~aidx[lane]);
        }
        if ((m1 >> lane) & 1u) {
            int pos = base + n0 + __popc(m1 & ltmask);
            if (pos < CCAP)
                g_cand[b][c][pos] =
                    ((unsigned long long)__float_as_uint(tile[32 + lane][c]) << 32)
                    | (unsigned)(~aidx[32 + lane]);
        }
    }
}

// ---------------------------------------------------------------------------
// Kernel C: per-(image,class) NMS + fused per-image top-100 (last block).
// ---------------------------------------------------------------------------
__global__ __launch_bounds__(256) void nms_class_kernel(
    const float* __restrict__ b1, const float* __restrict__ b2,
    const float* __restrict__ b3,
    const float* __restrict__ c1, const float* __restrict__ c2,
    const float* __restrict__ c3,
    const float* __restrict__ p1, const float* __restrict__ p2,
    const float* __restrict__ p3,
    float* __restrict__ out)
{
    __shared__ unsigned long long keys[CAND];                 // 4 KB (reused: keys2)
    __shared__ __align__(16) float4 cbox4[KTOP];              // 4 KB
    __shared__ float carea[KTOP], csc[KTOP];
    __shared__ int   keptslot[KTOP];
    __shared__ __align__(16) unsigned suppA[128 * 4];         // 2 KB (transposed, h=0)
    __shared__ __align__(16) unsigned suppB[128 * 4];         // 2 KB (transposed, h=1)
    __shared__ __align__(16) unsigned supp8[KTOP * 8];        // 8 KB (fallback/hist2)
    __shared__ int hist[256];                                 // (fallback/gsum)
    __shared__ int misc[16];
    __shared__ unsigned validm[8];
    __shared__ unsigned kw[4];
    __shared__ int schanged;

    const int b    = blockIdx.x / NC;
    const int c    = blockIdx.x % NC;
    const int tid  = threadIdx.x;
    const int lane = tid & 31;
    const unsigned ltmask = (1u << lane) - 1u;

    if (tid == 0) {
        misc[3] = 0; misc[12] = 0;
        misc[5] = g_candn[b][c];
        misc[6] = g_n74[b];
    }
    __syncthreads();

    const int cnt0 = misc[5];
    const bool good0 = (misc[6] <= ACAP) && (cnt0 >= 128 && cnt0 <= KTOP);

    if (good0) {
        // ---- direct load + hybrid bitonic sort of 256 keys, descending ----
        unsigned long long r = (tid < cnt0) ? g_cand[b][c][tid] : 0ull;
#pragma unroll
        for (int k = 2; k <= KTOP; k <<= 1) {
            for (int j = k >> 1; j > 0; j >>= 1) {
                unsigned long long v;
                if (j >= 32) {
                    keys[tid] = r;
                    __syncthreads();
                    v = keys[tid ^ j];
                    __syncthreads();
                } else {
                    v = __shfl_xor_sync(0xFFFFFFFFu, r, j);
                }
                bool up = ((tid & k) == 0) == ((tid & j) == 0);
                r = up ? (r > v ? r : v) : (r < v ? r : v);
            }
        }
        keys[tid] = r;
        __syncthreads();

        // ---- load boxes for top-256 ----
        unsigned long long mykey = r;
        bool valid = (mykey != 0ull);
        float sc = __uint_as_float((unsigned)(mykey >> 32));
        float4 bx = make_float4(0.f, 0.f, 0.f, 0.f);
        if (valid) {
            unsigned a = ~(unsigned)(mykey & 0xFFFFFFFFu);
            const float* bp; size_t off;
            if (a < N1)           { bp = b1; off = (size_t)(b * N1 + a) * 4; }
            else if (a < N1 + N2) { bp = b2; off = (size_t)(b * N2 + (a - N1)) * 4; }
            else                  { bp = b3; off = (size_t)(b * N3 + (a - N1 - N2)) * 4; }
            bx = *reinterpret_cast<const float4*>(bp + off);
        }
        cbox4[tid] = bx;
        carea[tid] = (bx.z - bx.x) * (bx.w - bx.y);
        csc[tid] = sc;
        keptslot[tid] = -1;
        {
            unsigned bal = __ballot_sync(0xFFFFFFFFu, valid);
            if (lane == 0) validm[tid >> 5] = bal;
        }
        __syncthreads();

        // ---- 128x128 triangle, TRANSPOSED (column j owns bits i<j),
        //      2 threads/column (parity on i), division-free exact test ----
        {
            const int j = tid & 127;
            const int h = tid >> 7;
            const float4 bj = cbox4[j];
            const float areaj = carea[j];
            unsigned w0 = 0u, w1 = 0u, w2 = 0u, w3 = 0u;
            for (int i = h; i < j; i += 2) {
                float4 bi = cbox4[i];
                float ai = carea[i];
                float iy = fmaxf(fminf(bi.z, bj.z) - fmaxf(bi.x, bj.x), 0.0f);
                float ix = fmaxf(fminf(bi.w, bj.w) - fmaxf(bi.y, bj.y), 0.0f);
                float inter = iy * ix;
                float uni = (ai + areaj) - inter;
                float hu  = 0.5f * uni;
                if (inter > hu) {
                    if (inter > hu * 1.0000002f) {
                        unsigned bit = 1u << (i & 31);
                        switch (i >> 5) {
                            case 0: w0 |= bit; break; case 1: w1 |= bit; break;
                            case 2: w2 |= bit; break; default: w3 |= bit; break;
                        }
                    } else {
                        misc[12] = 1;   // ambiguous rounding band
                    }
                }
            }
            uint4 wv = make_uint4(w0, w1, w2, w3);
            if (h == 0) *reinterpret_cast<uint4*>(&suppA[j * 4]) = wv;
            else        *reinterpret_cast<uint4*>(&suppB[j * 4]) = wv;
        }
        if (tid < 4) kw[tid] = validm[tid];   // x^0 = valid
        __syncthreads();

        // ---- Jacobi fixpoint: x_j = valid_j & !OR_{i<j}(suppT[j][i] & x_i).
        // Unique fixpoint == greedy NMS keep set; no-change => exact. ----
        {
            uint4 sa = make_uint4(0u, 0u, 0u, 0u);
            bool vj = false;
            if (tid < 128) {
                uint4 s0 = *reinterpret_cast<const uint4*>(&suppA[tid * 4]);
                uint4 s1 = *reinterpret_cast<const uint4*>(&suppB[tid * 4]);
                sa = make_uint4(s0.x | s1.x, s0.y | s1.y, s0.z | s1.z, s0.w | s1.w);
                vj = (validm[tid >> 5] >> (tid & 31)) & 1u;
            }
            int it = 0;
            for (; it < JMAX; it++) {
                unsigned k0 = kw[0], k1 = kw[1], k2 = kw[2], k3 = kw[3];
                bool nx = false;
                if (tid < 128) {
                    unsigned hitb = (sa.x & k0) | (sa.y & k1)
                                  | (sa.z & k2) | (sa.w & k3);
                    nx = vj && (hitb == 0u);
                }
                unsigned m = __ballot_sync(0xFFFFFFFFu, nx);
                __syncthreads();
                if (tid == 0) schanged = 0;
                __syncthreads();
                if (tid < 128 && lane == 0) {
                    if (m != kw[tid >> 5]) { kw[tid >> 5] = m; atomicOr(&schanged, 1); }
                }
                __syncthreads();
                if (!schanged) break;
            }
            if (it == JMAX && tid == 0) misc[12] = 1;
        }
        __syncthreads();

        // ---- rank kept candidates, gate on total>=100 ----
        if (misc[12] == 0) {
            unsigned k0 = kw[0], k1 = kw[1], k2 = kw[2], k3 = kw[3];
            int total = __popc(k0) + __popc(k1) + __popc(k2) + __popc(k3);
            if (tid < 128) {
                int w = tid >> 5;
                unsigned kwv = (w == 0) ? k0 : (w == 1) ? k1 : (w == 2) ? k2 : k3;
                if ((kwv >> (tid & 31)) & 1u) {
                    int rank = __popc(kwv & ((1u << (tid & 31)) - 1u));
                    if (w > 0) rank += __popc(k0);
                    if (w > 1) rank += __popc(k1);
                    if (w > 2) rank += __popc(k2);
                    if (rank < MAXPC) keptslot[tid] = rank;
                }
            }
            if (tid == 0) {
                if (total >= MAXPC) {
                    misc[3] = 1; misc[2] = MAXPC; g_cnt[b][c] = MAXPC;
                } else {
                    misc[3] = 0;
                }
            }
        }
        __syncthreads();
    }

    // ---- full exact fallback (never taken for this data) ----
    if (!good0 || misc[12] || !misc[3]) {
        hist[tid] = 0;
        if (tid == 0) { misc[1] = 0; misc[2] = 0; }
        keys[tid] = 0ull;
        keys[tid + 256] = 0ull;
        keptslot[tid] = -1;
        __syncthreads();
        for (int a = tid; a < NANCH; a += 256) {
            float cf;
            const float* pp; int o;
            if (a < N1)           { cf = c1[b * N1 + a]; pp = p1; o = b * N1 + a; }
            else if (a < N1 + N2) { cf = c2[b * N2 + (a - N1)]; pp = p2; o = b * N2 + (a - N1); }
            else                  { cf = c3[b * N3 + (a - N1 - N2)]; pp = p3; o = b * N3 + (a - N1 - N2); }
            if (cf > SCORE_THR) {
                float s = cf * __ldg(pp + (size_t)o * NC + c);
                if (s > SCORE_THR) {
                    int bk = (int)((s - SCORE_THR) * (256.0f / 0.7f));
                    bk = bk > 255 ? 255 : (bk < 0 ? 0 : bk);
                    atomicAdd(&hist[bk], 1);
                }
            }
        }
        __syncthreads();
        if (tid == 0) {
            int acc = 0, bbv = 0;
            for (int i = 255; i >= 0; --i) {
                acc += hist[i];
                if (acc >= KTOP) { bbv = i; break; }
            }
            misc[1] = bbv;
        }
        __syncthreads();
        const int bbv = misc[1];
        const int napad = (NANCH + 255) & ~255;
        for (int a = tid; a < napad; a += 256) {
            float s = 0.0f;
            bool pred = false;
            if (a < NANCH) {
                float cf;
                const float* pp; int o;
                if (a < N1)           { cf = c1[b * N1 + a]; pp = p1; o = b * N1 + a; }
                else if (a < N1 + N2) { cf = c2[b * N2 + (a - N1)]; pp = p2; o = b * N2 + (a - N1); }
                else                  { cf = c3[b * N3 + (a - N1 - N2)]; pp = p3; o = b * N3 + (a - N1 - N2); }
                if (cf > SCORE_THR) {
                    s = cf * __ldg(pp + (size_t)o * NC + c);
                    if (s > SCORE_THR) {
                        int bk = (int)((s - SCORE_THR) * (256.0f / 0.7f));
                        bk = bk > 255 ? 255 : (bk < 0 ? 0 : bk);
                        pred = (bk >= bbv);
                    }
                }
            }
            unsigned m = __ballot_sync(0xFFFFFFFFu, pred);
            if (pred) {
                int rank = __popc(m & ltmask);
                int base;
                if (rank == 0) base = atomicAdd(&misc[2], __popc(m));
                base = __shfl_sync(m, base, __ffs(m) - 1);
                int pos = base + rank;
                if (pos < CAND)
                    keys[pos] = ((unsigned long long)__float_as_uint(s) << 32)
                                | (unsigned)(~(unsigned)a);
            }
        }
        __syncthreads();
        if (tid == 0) misc[2] = 0;

        for (int k = 2; k <= CAND; k <<= 1) {
            for (int j = k >> 1; j > 0; j >>= 1) {
                int i = ((tid & ~(j - 1)) << 1) | (tid & (j - 1));
                int p = i | j;
                unsigned long long va = keys[i], vb = keys[p];
                if ((va < vb) == ((i & k) == 0)) { keys[i] = vb; keys[p] = va; }
                __syncthreads();
            }
        }

        unsigned long long mykey = keys[tid];
        bool valid = (mykey != 0ull);
        float sc = __uint_as_float((unsigned)(mykey >> 32));
        float4 bx = make_float4(0.f, 0.f, 0.f, 0.f);
        if (valid) {
            unsigned a = ~(unsigned)(mykey & 0xFFFFFFFFu);
            const float* bp; size_t off;
            if (a < N1)           { bp = b1; off = (size_t)(b * N1 + a) * 4; }
            else if (a < N1 + N2) { bp = b2; off = (size_t)(b * N2 + (a - N1)) * 4; }
            else                  { bp = b3; off = (size_t)(b * N3 + (a - N1 - N2)) * 4; }
            bx = *reinterpret_cast<const float4*>(bp + off);
        }
        cbox4[tid] = bx;
        carea[tid] = (bx.z - bx.x) * (bx.w - bx.y);
        csc[tid] = sc;
        keptslot[tid] = -1;
        {
            unsigned bal = __ballot_sync(0xFFFFFFFFu, valid);
            if (lane == 0) validm[tid >> 5] = bal;
        }
        __syncthreads();

        {
            const int i = tid;
            const float4 bi = cbox4[i];
            const float areai = carea[i];
            unsigned words[8];
#pragma unroll
            for (int w = 0; w < 8; w++) words[w] = 0u;
            for (int j = i + 1; j < KTOP; j++) {
                float4 bj = cbox4[j];
                float aj = carea[j];
                float iy = fmaxf(fminf(bi.z, bj.z) - fmaxf(bi.x, bj.x), 0.0f);
                float ix = fmaxf(fminf(bi.w, bj.w) - fmaxf(bi.y, bj.y), 0.0f);
                float inter = iy * ix;
                float uni = (areai + aj) - inter;
                if (uni > 0.0f) {
                    float iou = inter / uni;
                    if (iou > IOU_THR) words[j >> 5] |= (1u << (j & 31));
                }
            }
            uint4* sp = reinterpret_cast<uint4*>(&supp8[i * 8]);
            sp[0] = make_uint4(words[0], words[1], words[2], words[3]);
            sp[1] = make_uint4(words[4], words[5], words[6], words[7]);
        }
        __syncthreads();
        if (tid == 0) {
            unsigned kk[8];
#pragma unroll
            for (int w = 0; w < 8; w++) kk[w] = validm[w];
            int count = 0;
            for (int w = 0; w < 8; w++) {
                unsigned cw = kk[w];
                while (cw) {
                    int bit = __ffs(cw) - 1;
                    int i2 = (w << 5) + bit;
                    count++;
                    if (count <= MAXPC) keptslot[i2] = count - 1;
                    uint4 r0 = *reinterpret_cast<const uint4*>(&supp8[i2 * 8]);
                    uint4 r1 = *reinterpret_cast<const uint4*>(&supp8[i2 * 8 + 4]);
                    kk[0] &= ~r0.x; kk[1] &= ~r0.y; kk[2] &= ~r0.z; kk[3] &= ~r0.w;
                    kk[4] &= ~r1.x; kk[5] &= ~r1.y; kk[6] &= ~r1.z; kk[7] &= ~r1.w;
                    unsigned above = (bit == 31) ? 0u : (0xFFFFFFFFu << (bit + 1));
                    cw = kk[w] & above;
                }
            }
            int cc2 = count > MAXPC ? MAXPC : count;
            misc[2] = cc2;
            g_cnt[b][c] = cc2;
        }
        __syncthreads();
    }

    // ---- epilogue: kept writes + NEG tail + topk candidate append ----
    {
        int r2 = keptslot[tid];
        bool kept = (r2 >= 0 && r2 < MAXPC);
        if (kept) {
            g_sc[b][c * MAXPC + r2]  = csc[tid];
            g_box[b][c * MAXPC + r2] = cbox4[tid];
        }
        int cf = misc[2];
        if (tid >= cf && tid < MAXPC) g_sc[b][c * MAXPC + tid] = NEGV;

        bool tp = kept && (csc[tid] > TTHR);
        unsigned m = __ballot_sync(0xFFFFFFFFu, tp);
        if (tp) {
            int rank = __popc(m & ltmask);
            int base;
            if (rank == 0) base = atomicAdd(&g_ntop[b], __popc(m));
            base = __shfl_sync(m, base, __ffs(m) - 1);
            int pos = base + rank;
            if (pos < KTOP) {
                unsigned s_idx = (unsigned)(c * MAXPC + r2);
                g_topc[b][pos] = ((unsigned long long)__float_as_uint(csc[tid]) << 32)
                                 | (unsigned)(~s_idx);
            }
        }
    }

    // ---- last-block-done: fused per-image top-100 ----
    __threadfence();
    __syncthreads();
    if (tid == 0) misc[7] = atomicAdd(&g_done[b], 1);
    __syncthreads();
    if (misc[7] != NC - 1) return;

    unsigned long long* keys2 = keys;
    int* hist2 = reinterpret_cast<int*>(supp8);
    int* gsum  = hist;

    if (tid == 0) { misc[8] = 0; misc[9] = 0; misc[10] = g_ntop[b]; }
    __syncthreads();
    if (tid < NC) atomicAdd(&misc[9], g_cnt[b][tid]);

    const int gcnt = misc[10];
    const bool tgood = (gcnt >= MAXTOT && gcnt <= KTOP);

    if (tgood) {
        unsigned long long r = (tid < gcnt) ? g_topc[b][tid] : 0ull;
#pragma unroll
        for (int k = 2; k <= KTOP; k <<= 1) {
            for (int j = k >> 1; j > 0; j >>= 1) {
                unsigned long long v;
                if (j >= 32) {
                    keys2[tid] = r;
                    __syncthreads();
                    v = keys2[tid ^ j];
                    __syncthreads();
                } else {
                    v = __shfl_xor_sync(0xFFFFFFFFu, r, j);
                }
                bool up = ((tid & k) == 0) == ((tid & j) == 0);
                r = up ? (r > v ? r : v) : (r < v ? r : v);
            }
        }
        keys2[tid] = r;
        __syncthreads();
    } else {
        const float4* gs4 = reinterpret_cast<const float4*>(&g_sc[b][0]);
#pragma unroll
        for (int k = 0; k < 8; k++) hist2[tid + k * 256] = 0;
        keys2[tid] = 0ull;
        keys2[tid + 256] = 0ull;
        __syncthreads();
#pragma unroll
        for (int k = 0; k < 8; k++) {
            int t = tid + k * 256;
            if (t < (NC * MAXPC) / 4) {
                float4 v = gs4[t];
                float sv[4] = {v.x, v.y, v.z, v.w};
#pragma unroll
                for (int q = 0; q < 4; q++) {
                    float s = sv[q];
                    if (s > SCORE_THR) {
                        int bk = (int)((s - SCORE_THR) * ((float)FBINS / 0.7f));
                        bk = bk > FBINS - 1 ? FBINS - 1 : (bk < 0 ? 0 : bk);
                        atomicAdd(&hist2[bk], 1);
                    }
                }
            }
        }
        __syncthreads();
        if (tid < 64) {
            int s = 0;
#pragma unroll
            for (int k = 0; k < 32; k++) s += hist2[tid * 32 + k];
            gsum[tid] = s;
        }
        __syncthreads();
        if (tid == 0) {
            int acc = 0, g = -1, bbv = 0;
            for (int i = 63; i >= 0; i--) {
                if (acc + gsum[i] >= MAXTOT) { g = i; break; }
                acc += gsum[i];
            }
            if (g >= 0) {
                for (int k = 31; k >= 0; k--) {
                    acc += hist2[g * 32 + k];
                    if (acc >= MAXTOT) { bbv = g * 32 + k; break; }
                }
            }
            misc[11] = bbv;
        }
        __syncthreads();
        const int bb = misc[11];
#pragma unroll
        for (int k = 0; k < 8; k++) {
            int t = tid + k * 256;
            if (t < (NC * MAXPC) / 4) {
                float4 v = gs4[t];
                float sv[4] = {v.x, v.y, v.z, v.w};
#pragma unroll
                for (int q = 0; q < 4; q++) {
                    float s = sv[q];
                    if (s > SCORE_THR) {
                        int bk = (int)((s - SCORE_THR) * ((float)FBINS / 0.7f));
                        bk = bk > FBINS - 1 ? FBINS - 1 : (bk < 0 ? 0 : bk);
                        if (bk >= bb) {
                            int pos = atomicAdd(&misc[8], 1);
                            if (pos < CAND) {
                                unsigned s_idx = (unsigned)(t * 4 + q);
                                keys2[pos] =
                                    ((unsigned long long)__float_as_uint(s) << 32)
                                    | (unsigned)(~s_idx);
                            }
                        }
                    }
                }
            }
        }
        __syncthreads();
        for (int k = 2; k <= CAND; k <<= 1) {
            for (int j = k >> 1; j > 0; j >>= 1) {
                for (int v = tid; v < (CAND >> 1); v += 256) {
                    int i = ((v & ~(j - 1)) << 1) | (v & (j - 1));
                    int p = i | j;
                    unsigned long long va = keys2[i], vb = keys2[p];
                    if ((va < vb) == ((i & k) == 0)) { keys2[i] = vb; keys2[p] = va; }
                }
                __syncthreads();
            }
        }
    }

    float* ob = out;
    float* os = out + NB * MAXTOT * 4;
    float* oc = os + NB * MAXTOT;
    float* on = oc + NB * MAXTOT;

    if (tid < MAXTOT) {
        unsigned long long key = keys2[tid];
        float sco = 0.0f, cl = 0.0f;
        float bx0 = 0.f, bx1 = 0.f, bx2 = 0.f, bx3 = 0.f;
        if (key != 0ull) {
            sco = __uint_as_float((unsigned)(key >> 32));
            unsigned s = ~(unsigned)(key & 0xFFFFFFFFu);
            cl = (float)(s / MAXPC);
            float4 bbx = g_box[b][s];
            bx0 = fminf(fmaxf(bbx.x, 0.0f), 1.0f);
            bx1 = fminf(fmaxf(bbx.y, 0.0f), 1.0f);
            bx2 = fminf(fmaxf(bbx.z, 0.0f), 1.0f);
            bx3 = fminf(fmaxf(bbx.w, 0.0f), 1.0f);
        }
        size_t base = (size_t)(b * MAXTOT + tid) * 4;
        ob[base + 0] = bx0; ob[base + 1] = bx1; ob[base + 2] = bx2; ob[base + 3] = bx3;
        os[b * MAXTOT + tid] = sco;
        oc[b * MAXTOT + tid] = cl;
    }
    if (tid < NC) g_candn[b][tid] = 0;
    if (tid == 0) {
        int tot = misc[9];
        on[b] = (float)(tot > MAXTOT ? MAXTOT : tot);
        g_n74[b] = 0; g_ntop[b] = 0; g_done[b] = 0;
    }
}

extern "C" void kernel_launch(void* const* d_in, const int* in_sizes, int n_in,
                              void* d_out, int out_size)
{
    const float* b1 = (const float*)d_in[0];
    const float* c1 = (const float*)d_in[1];
    const float* p1 = (const float*)d_in[2];
    const float* b2 = (const float*)d_in[3];
    const float* c2 = (const float*)d_in[4];
    const float* p2 = (const float*)d_in[5];
    const float* b3 = (const float*)d_in[6];
    const float* c3 = (const float*)d_in[7];
    const float* p3 = (const float*)d_in[8];

    dim3 cgrid(42, NB);
    compact_kernel<<<cgrid, 256>>>(c1, c2, c3);
    dim3 fgrid(64, NB);
    score_filter_kernel<<<fgrid, 256>>>(p1, p2, p3);
    nms_class_kernel<<<NB * NC, 256>>>(b1, b2, b3, c1, c2, c3,
                                       p1, p2, p3, (float*)d_out);
}